// round 2
// baseline (speedup 1.0000x reference)
#include <cuda_runtime.h>
#include <math.h>

#define NN 4096
#define DD 2048
#define MARGIN 0.3f

#define BM 128
#define BN 128
#define BK 16
#define PAD 4
#define LDSW (BM + PAD)   // 132 floats per k-row, breaks bank conflicts

// Scratch (allocation-free rule: device globals)
__device__ float g_sq[NN];
__device__ float g_rowmax[NN];   // hardest-positive distance per anchor
__device__ float g_rowmin[NN];   // hardest-negative distance per anchor

// ---------------------------------------------------------------------------
// Kernel 1: per-row squared norms + init of the max/min accumulators
// ---------------------------------------------------------------------------
__global__ void prep_kernel(const float* __restrict__ X) {
    int row = blockIdx.x;
    const float4* xr = reinterpret_cast<const float4*>(X + (size_t)row * DD);
    float s = 0.f;
#pragma unroll
    for (int c = 0; c < 4; ++c) {
        float4 v = xr[threadIdx.x + c * 128];
        s += v.x * v.x + v.y * v.y + v.z * v.z + v.w * v.w;
    }
#pragma unroll
    for (int off = 16; off; off >>= 1)
        s += __shfl_xor_sync(0xffffffffu, s, off);
    __shared__ float ws[4];
    int w = threadIdx.x >> 5, l = threadIdx.x & 31;
    if (l == 0) ws[w] = s;
    __syncthreads();
    if (threadIdx.x == 0) {
        g_sq[row] = ws[0] + ws[1] + ws[2] + ws[3];
        g_rowmax[row] = 0.f;
        g_rowmin[row] = __int_as_float(0x7f800000);  // +inf
    }
}

// ---------------------------------------------------------------------------
// Kernel 2: fused Gram-tile GEMM + distance + batch-hard mining epilogue.
// 128x128 tile, BK=16, 256 threads, 8x8 per-thread micro-tile (4+4 split).
// ---------------------------------------------------------------------------
__global__ __launch_bounds__(256) void triplet_tile_kernel(
    const float* __restrict__ X, const int* __restrict__ labels)
{
    __shared__ float sA[BK][LDSW];
    __shared__ float sB[BK][LDSW];
    __shared__ float sSqR[BM], sSqC[BN];
    __shared__ int   sLabR[BM], sLabC[BN];

    const int bi = blockIdx.y * BM;
    const int bj = blockIdx.x * BN;
    const int tid = threadIdx.x;
    const int tx = tid & 15;       // 0..15 -> col groups
    const int ty = tid >> 4;       // 0..15 -> row groups

    if (tid < 128) {
        sLabR[tid] = labels[bi + tid];
        sSqR[tid]  = g_sq[bi + tid];
    } else {
        int t = tid - 128;
        sLabC[t] = labels[bj + t];
        sSqC[t]  = g_sq[bj + t];
    }

    // Global-load mapping: 4 threads per row, each a float4 of the BK slice
    const int lrow = tid >> 2;         // 0..63
    const int lk   = (tid & 3) << 2;   // 0,4,8,12

    const float* A0 = X + (size_t)(bi + lrow)      * DD + lk;
    const float* A1 = X + (size_t)(bi + lrow + 64) * DD + lk;
    const float* B0 = X + (size_t)(bj + lrow)      * DD + lk;
    const float* B1 = X + (size_t)(bj + lrow + 64) * DD + lk;

    float acc[8][8];
#pragma unroll
    for (int m = 0; m < 8; ++m)
#pragma unroll
        for (int n = 0; n < 8; ++n) acc[m][n] = 0.f;

    for (int k0 = 0; k0 < DD; k0 += BK) {
        float4 a0 = *(const float4*)(A0 + k0);
        float4 a1 = *(const float4*)(A1 + k0);
        float4 b0 = *(const float4*)(B0 + k0);
        float4 b1 = *(const float4*)(B1 + k0);

        sA[lk + 0][lrow] = a0.x; sA[lk + 1][lrow] = a0.y;
        sA[lk + 2][lrow] = a0.z; sA[lk + 3][lrow] = a0.w;
        sA[lk + 0][lrow + 64] = a1.x; sA[lk + 1][lrow + 64] = a1.y;
        sA[lk + 2][lrow + 64] = a1.z; sA[lk + 3][lrow + 64] = a1.w;

        sB[lk + 0][lrow] = b0.x; sB[lk + 1][lrow] = b0.y;
        sB[lk + 2][lrow] = b0.z; sB[lk + 3][lrow] = b0.w;
        sB[lk + 0][lrow + 64] = b1.x; sB[lk + 1][lrow + 64] = b1.y;
        sB[lk + 2][lrow + 64] = b1.z; sB[lk + 3][lrow + 64] = b1.w;

        __syncthreads();

#pragma unroll
        for (int k = 0; k < BK; ++k) {
            float4 af0 = *(const float4*)&sA[k][ty * 4];
            float4 af1 = *(const float4*)&sA[k][64 + ty * 4];
            float4 bf0 = *(const float4*)&sB[k][tx * 4];
            float4 bf1 = *(const float4*)&sB[k][64 + tx * 4];
            float a[8] = {af0.x, af0.y, af0.z, af0.w, af1.x, af1.y, af1.z, af1.w};
            float b[8] = {bf0.x, bf0.y, bf0.z, bf0.w, bf1.x, bf1.y, bf1.z, bf1.w};
#pragma unroll
            for (int m = 0; m < 8; ++m)
#pragma unroll
                for (int n = 0; n < 8; ++n)
                    acc[m][n] = fmaf(a[m], b[n], acc[m][n]);
        }
        __syncthreads();
    }

    // Epilogue: distances + label-masked max/min, reduce across the 16 threads
    // sharing each row (contiguous 16-lane groups -> width-16 shuffles).
    const float INF = __int_as_float(0x7f800000);
#pragma unroll
    for (int m = 0; m < 8; ++m) {
        const int r   = (m < 4) ? (ty * 4 + m) : (64 + ty * 4 + m - 4);
        const int li  = sLabR[r];
        const float sqi = sSqR[r];
        float mx = 0.f, mn = INF;
#pragma unroll
        for (int n = 0; n < 8; ++n) {
            const int c = (n < 4) ? (tx * 4 + n) : (64 + tx * 4 + n - 4);
            float d2 = sqi + sSqC[c] - 2.f * acc[m][n];
            d2 = fmaxf(d2, 0.f);
            float d = (d2 > 0.f) ? sqrtf(d2) : 0.f;
            if (li == sLabC[c]) mx = fmaxf(mx, d);
            else                mn = fminf(mn, d);
        }
#pragma unroll
        for (int off = 8; off; off >>= 1) {
            mx = fmaxf(mx, __shfl_xor_sync(0xffffffffu, mx, off, 16));
            mn = fminf(mn, __shfl_xor_sync(0xffffffffu, mn, off, 16));
        }
        if (tx == 0) {
            // non-negative floats: int-ordered compare == float-ordered compare
            atomicMax((int*)&g_rowmax[bi + r], __float_as_int(mx));
            atomicMin((int*)&g_rowmin[bi + r], __float_as_int(mn));
        }
    }
}

// ---------------------------------------------------------------------------
// Kernel 3: final margin-ranking reduction to a scalar
// ---------------------------------------------------------------------------
__global__ void finalize_kernel(float* __restrict__ out) {
    const float INF = __int_as_float(0x7f800000);
    float sum = 0.f;
    int cnt = 0;
    for (int i = threadIdx.x; i < NN; i += 256) {
        float ap = g_rowmax[i];
        float an = g_rowmin[i];
        if (ap > 0.f && an < INF) {
            float pa = ap - an + MARGIN;
            sum += (pa > 0.f) ? pa : 0.f;
            cnt += 1;
        }
    }
#pragma unroll
    for (int off = 16; off; off >>= 1) {
        sum += __shfl_xor_sync(0xffffffffu, sum, off);
        cnt += __shfl_xor_sync(0xffffffffu, cnt, off);
    }
    __shared__ float ssum[8];
    __shared__ int   scnt[8];
    int w = threadIdx.x >> 5, l = threadIdx.x & 31;
    if (l == 0) { ssum[w] = sum; scnt[w] = cnt; }
    __syncthreads();
    if (threadIdx.x == 0) {
        float s = 0.f; int c = 0;
#pragma unroll
        for (int i = 0; i < 8; ++i) { s += ssum[i]; c += scnt[i]; }
        out[0] = (c > 0) ? (s / (float)c) : 0.f;
    }
}

// ---------------------------------------------------------------------------
extern "C" void kernel_launch(void* const* d_in, const int* in_sizes, int n_in,
                              void* d_out, int out_size) {
    const float* X      = (const float*)d_in[0];
    const int*   labels = (const int*)d_in[1];
    float* out = (float*)d_out;

    prep_kernel<<<NN, 128>>>(X);
    dim3 grid(NN / BN, NN / BM);
    triplet_tile_kernel<<<grid, 256>>>(X, labels);
    finalize_kernel<<<1, 256>>>(out);
}

// round 3
// speedup vs baseline: 1.6103x; 1.6103x over previous
#include <cuda_runtime.h>
#include <math.h>

#define NN 4096
#define DD 2048
#define MARGIN 0.3f

#define BM 128
#define BN 128
#define BK 16
#define PAD 4
#define LDSW (BM + PAD)   // 132 floats per k-row, breaks bank conflicts

#define NB (NN / BM)              // 32 blocks per dim
#define NTRI (NB * (NB + 1) / 2)  // 528 upper-triangle tiles

// Scratch (allocation-free rule: device globals)
__device__ float g_sq[NN];
__device__ float g_rowmax[NN];   // hardest-positive distance per anchor
__device__ float g_rowmin[NN];   // hardest-negative distance per anchor

// ---------------------------------------------------------------------------
// Kernel 1: per-row squared norms + init of the max/min accumulators
// ---------------------------------------------------------------------------
__global__ void prep_kernel(const float* __restrict__ X) {
    int row = blockIdx.x;
    const float4* xr = reinterpret_cast<const float4*>(X + (size_t)row * DD);
    float s = 0.f;
#pragma unroll
    for (int c = 0; c < 4; ++c) {
        float4 v = xr[threadIdx.x + c * 128];
        s += v.x * v.x + v.y * v.y + v.z * v.z + v.w * v.w;
    }
#pragma unroll
    for (int off = 16; off; off >>= 1)
        s += __shfl_xor_sync(0xffffffffu, s, off);
    __shared__ float ws[4];
    int w = threadIdx.x >> 5, l = threadIdx.x & 31;
    if (l == 0) ws[w] = s;
    __syncthreads();
    if (threadIdx.x == 0) {
        g_sq[row] = ws[0] + ws[1] + ws[2] + ws[3];
        g_rowmax[row] = 0.f;
        g_rowmin[row] = __int_as_float(0x7f800000);  // +inf
    }
}

// ---------------------------------------------------------------------------
// Kernel 2: fused Gram-tile GEMM + distance + batch-hard mining epilogue.
// Upper-triangle tiles only (dist symmetric, mask symmetric): each
// off-diagonal tile feeds both row-anchors (shuffle reduce) and
// column-anchors (smem atomic reduce).
// ---------------------------------------------------------------------------
__global__ __launch_bounds__(256) void triplet_tile_kernel(
    const float* __restrict__ X, const int* __restrict__ labels)
{
    __shared__ float sA[BK][LDSW];
    __shared__ float sB[BK][LDSW];
    __shared__ float sSqR[BM], sSqC[BN];
    __shared__ int   sLabR[BM], sLabC[BN];
    __shared__ int   sColMax[BN], sColMin[BN];

    // Decode linear triangle index -> (p, q) with p <= q
    const int t = blockIdx.x;
    int q = (int)((sqrtf(8.f * (float)t + 1.f) - 1.f) * 0.5f);
    while ((q + 1) * (q + 2) / 2 <= t) ++q;
    while (q * (q + 1) / 2 > t) --q;
    const int p = t - q * (q + 1) / 2;

    const int bi = p * BM;           // row block (anchors i)
    const int bj = q * BN;           // col block (anchors j), bi <= bj
    const bool diag = (p == q);

    const int tid = threadIdx.x;
    const int tx = tid & 15;       // 0..15 -> col groups
    const int ty = tid >> 4;       // 0..15 -> row groups
    const int INFI = 0x7f800000;

    if (tid < 128) {
        sLabR[tid] = labels[bi + tid];
        sSqR[tid]  = g_sq[bi + tid];
        sColMax[tid] = 0;
        sColMin[tid] = INFI;
    } else {
        int c = tid - 128;
        sLabC[c] = labels[bj + c];
        sSqC[c]  = g_sq[bj + c];
    }

    // Global-load mapping: 4 threads per row, each a float4 of the BK slice
    const int lrow = tid >> 2;         // 0..63
    const int lk   = (tid & 3) << 2;   // 0,4,8,12

    const float* A0 = X + (size_t)(bi + lrow)      * DD + lk;
    const float* A1 = X + (size_t)(bi + lrow + 64) * DD + lk;
    const float* B0 = X + (size_t)(bj + lrow)      * DD + lk;
    const float* B1 = X + (size_t)(bj + lrow + 64) * DD + lk;

    float acc[8][8];
#pragma unroll
    for (int m = 0; m < 8; ++m)
#pragma unroll
        for (int n = 0; n < 8; ++n) acc[m][n] = 0.f;

    for (int k0 = 0; k0 < DD; k0 += BK) {
        float4 a0 = *(const float4*)(A0 + k0);
        float4 a1 = *(const float4*)(A1 + k0);
        float4 b0 = *(const float4*)(B0 + k0);
        float4 b1 = *(const float4*)(B1 + k0);

        sA[lk + 0][lrow] = a0.x; sA[lk + 1][lrow] = a0.y;
        sA[lk + 2][lrow] = a0.z; sA[lk + 3][lrow] = a0.w;
        sA[lk + 0][lrow + 64] = a1.x; sA[lk + 1][lrow + 64] = a1.y;
        sA[lk + 2][lrow + 64] = a1.z; sA[lk + 3][lrow + 64] = a1.w;

        sB[lk + 0][lrow] = b0.x; sB[lk + 1][lrow] = b0.y;
        sB[lk + 2][lrow] = b0.z; sB[lk + 3][lrow] = b0.w;
        sB[lk + 0][lrow + 64] = b1.x; sB[lk + 1][lrow + 64] = b1.y;
        sB[lk + 2][lrow + 64] = b1.z; sB[lk + 3][lrow + 64] = b1.w;

        __syncthreads();

#pragma unroll
        for (int k = 0; k < BK; ++k) {
            float4 af0 = *(const float4*)&sA[k][ty * 4];
            float4 af1 = *(const float4*)&sA[k][64 + ty * 4];
            float4 bf0 = *(const float4*)&sB[k][tx * 4];
            float4 bf1 = *(const float4*)&sB[k][64 + tx * 4];
            float a[8] = {af0.x, af0.y, af0.z, af0.w, af1.x, af1.y, af1.z, af1.w};
            float b[8] = {bf0.x, bf0.y, bf0.z, bf0.w, bf1.x, bf1.y, bf1.z, bf1.w};
#pragma unroll
            for (int m = 0; m < 8; ++m)
#pragma unroll
                for (int n = 0; n < 8; ++n)
                    acc[m][n] = fmaf(a[m], b[n], acc[m][n]);
        }
        __syncthreads();
    }

    // Epilogue: distance + label-masked max/min.
    // Row side: width-16 shuffles (threads sharing a row are contiguous lanes).
    // Col side: per-thread partials -> smem int-atomics (only off-diagonal).
    const float INF = __int_as_float(INFI);
    float cmx[8], cmn[8];
#pragma unroll
    for (int n = 0; n < 8; ++n) { cmx[n] = 0.f; cmn[n] = INF; }

#pragma unroll
    for (int m = 0; m < 8; ++m) {
        const int r   = (m < 4) ? (ty * 4 + m) : (64 + ty * 4 + m - 4);
        const int li  = sLabR[r];
        const float sqi = sSqR[r];
        float mx = 0.f, mn = INF;
#pragma unroll
        for (int n = 0; n < 8; ++n) {
            const int c = (n < 4) ? (tx * 4 + n) : (64 + tx * 4 + n - 4);
            float d2 = sqi + sSqC[c] - 2.f * acc[m][n];
            d2 = fmaxf(d2, 0.f);
            float d = (d2 > 0.f) ? sqrtf(d2) : 0.f;
            if (li == sLabC[c]) {
                mx = fmaxf(mx, d);
                cmx[n] = fmaxf(cmx[n], d);
            } else {
                mn = fminf(mn, d);
                cmn[n] = fminf(cmn[n], d);
            }
        }
#pragma unroll
        for (int off = 8; off; off >>= 1) {
            mx = fmaxf(mx, __shfl_xor_sync(0xffffffffu, mx, off, 16));
            mn = fminf(mn, __shfl_xor_sync(0xffffffffu, mn, off, 16));
        }
        if (tx == 0) {
            // non-negative floats: int-ordered compare == float-ordered compare
            atomicMax((int*)&g_rowmax[bi + r], __float_as_int(mx));
            atomicMin((int*)&g_rowmin[bi + r], __float_as_int(mn));
        }
    }

    if (!diag) {
#pragma unroll
        for (int n = 0; n < 8; ++n) {
            const int c = (n < 4) ? (tx * 4 + n) : (64 + tx * 4 + n - 4);
            if (cmx[n] > 0.f) atomicMax(&sColMax[c], __float_as_int(cmx[n]));
            if (cmn[n] < INF) atomicMin(&sColMin[c], __float_as_int(cmn[n]));
        }
        __syncthreads();
        if (tid < 128) {
            int vmx = sColMax[tid];
            int vmn = sColMin[tid];
            if (vmx != 0)    atomicMax((int*)&g_rowmax[bj + tid], vmx);
            if (vmn != INFI) atomicMin((int*)&g_rowmin[bj + tid], vmn);
        }
    }
}

// ---------------------------------------------------------------------------
// Kernel 3: final margin-ranking reduction to a scalar
// ---------------------------------------------------------------------------
__global__ void finalize_kernel(float* __restrict__ out) {
    const float INF = __int_as_float(0x7f800000);
    float sum = 0.f;
    int cnt = 0;
    for (int i = threadIdx.x; i < NN; i += 256) {
        float ap = g_rowmax[i];
        float an = g_rowmin[i];
        if (ap > 0.f && an < INF) {
            float pa = ap - an + MARGIN;
            sum += (pa > 0.f) ? pa : 0.f;
            cnt += 1;
        }
    }
#pragma unroll
    for (int off = 16; off; off >>= 1) {
        sum += __shfl_xor_sync(0xffffffffu, sum, off);
        cnt += __shfl_xor_sync(0xffffffffu, cnt, off);
    }
    __shared__ float ssum[8];
    __shared__ int   scnt[8];
    int w = threadIdx.x >> 5, l = threadIdx.x & 31;
    if (l == 0) { ssum[w] = sum; scnt[w] = cnt; }
    __syncthreads();
    if (threadIdx.x == 0) {
        float s = 0.f; int c = 0;
#pragma unroll
        for (int i = 0; i < 8; ++i) { s += ssum[i]; c += scnt[i]; }
        out[0] = (c > 0) ? (s / (float)c) : 0.f;
    }
}

// ---------------------------------------------------------------------------
extern "C" void kernel_launch(void* const* d_in, const int* in_sizes, int n_in,
                              void* d_out, int out_size) {
    const float* X      = (const float*)d_in[0];
    const int*   labels = (const int*)d_in[1];
    float* out = (float*)d_out;

    prep_kernel<<<NN, 128>>>(X);
    triplet_tile_kernel<<<NTRI, 256>>>(X, labels);
    finalize_kernel<<<1, 256>>>(out);
}